// round 1
// baseline (speedup 1.0000x reference)
#include <cuda_runtime.h>
#include <math.h>

// Problem constants
#define S_LEN 2048
#define DMODEL 2048
#define NHEADS 16
#define DKH 128
#define BATCH 2
#define MROWS (BATCH * S_LEN)   // 4096

// fp32 value of sqrt(2048) as computed in fp32 by the reference
#define SQRT_DM 45.254833995939045f

// Scratch (allocation-free rule: __device__ globals). 4 x 33.5MB.
__device__ float g_q[(size_t)MROWS * DMODEL];
__device__ float g_k[(size_t)MROWS * DMODEL];
__device__ float g_v[(size_t)MROWS * DMODEL];
__device__ float g_o[(size_t)MROWS * DMODEL];

// ---------------------------------------------------------------------------
// GEMM: C[m,n] = sum_k A[m,k] * W[n,k] + bias[n]
// A: [4096, 2048] row-major, W: [2048, 2048] row-major, C: [4096, 2048].
// Tile 128x128x16, 256 threads, 8x8 micro-tile, smem stored transposed [k][m].
// ---------------------------------------------------------------------------
__global__ __launch_bounds__(256) void gemm_nt_bias(
    const float* __restrict__ A, const float* __restrict__ W,
    const float* __restrict__ bias, float* __restrict__ C)
{
    const int K = DMODEL;
    const int N = DMODEL;

    __shared__ float As[16][132];
    __shared__ float Bs[16][132];

    const int tid = threadIdx.x;
    const int tr  = tid >> 4;          // 0..15
    const int tc  = tid & 15;          // 0..15
    const int bm  = blockIdx.y << 7;
    const int bn  = blockIdx.x << 7;

    const int lr = tid >> 2;           // loader row 0..63
    const int lk = (tid & 3) << 2;     // loader k-offset 0,4,8,12

    const float* Ar0 = A + (size_t)(bm + lr) * K + lk;
    const float* Ar1 = A + (size_t)(bm + 64 + lr) * K + lk;
    const float* Wr0 = W + (size_t)(bn + lr) * K + lk;
    const float* Wr1 = W + (size_t)(bn + 64 + lr) * K + lk;

    float acc[8][8];
#pragma unroll
    for (int i = 0; i < 8; i++)
#pragma unroll
        for (int j = 0; j < 8; j++) acc[i][j] = 0.f;

    // prefetch first tile into registers
    float4 pa0 = *(const float4*)(Ar0);
    float4 pa1 = *(const float4*)(Ar1);
    float4 pb0 = *(const float4*)(Wr0);
    float4 pb1 = *(const float4*)(Wr1);

    for (int kt = 0; kt < K; kt += 16) {
        // stage registers -> smem (transposed)
        As[lk + 0][lr] = pa0.x; As[lk + 1][lr] = pa0.y;
        As[lk + 2][lr] = pa0.z; As[lk + 3][lr] = pa0.w;
        As[lk + 0][64 + lr] = pa1.x; As[lk + 1][64 + lr] = pa1.y;
        As[lk + 2][64 + lr] = pa1.z; As[lk + 3][64 + lr] = pa1.w;
        Bs[lk + 0][lr] = pb0.x; Bs[lk + 1][lr] = pb0.y;
        Bs[lk + 2][lr] = pb0.z; Bs[lk + 3][lr] = pb0.w;
        Bs[lk + 0][64 + lr] = pb1.x; Bs[lk + 1][64 + lr] = pb1.y;
        Bs[lk + 2][64 + lr] = pb1.z; Bs[lk + 3][64 + lr] = pb1.w;
        __syncthreads();

        if (kt + 16 < K) {
            pa0 = *(const float4*)(Ar0 + kt + 16);
            pa1 = *(const float4*)(Ar1 + kt + 16);
            pb0 = *(const float4*)(Wr0 + kt + 16);
            pb1 = *(const float4*)(Wr1 + kt + 16);
        }

#pragma unroll
        for (int k = 0; k < 16; k++) {
            float4 x0 = *(const float4*)&As[k][tr << 2];
            float4 x1 = *(const float4*)&As[k][64 + (tr << 2)];
            float4 y0 = *(const float4*)&Bs[k][tc << 2];
            float4 y1 = *(const float4*)&Bs[k][64 + (tc << 2)];
            float av[8] = {x0.x, x0.y, x0.z, x0.w, x1.x, x1.y, x1.z, x1.w};
            float bv[8] = {y0.x, y0.y, y0.z, y0.w, y1.x, y1.y, y1.z, y1.w};
#pragma unroll
            for (int i = 0; i < 8; i++)
#pragma unroll
                for (int j = 0; j < 8; j++) acc[i][j] += av[i] * bv[j];
        }
        __syncthreads();
    }

    // epilogue with bias
#pragma unroll
    for (int i = 0; i < 8; i++) {
        int row = bm + ((i < 4) ? ((tr << 2) + i) : (64 + (tr << 2) + i - 4));
#pragma unroll
        for (int jh = 0; jh < 2; jh++) {
            int col = bn + (jh ? (64 + (tc << 2)) : (tc << 2));
            float4 r;
            r.x = acc[i][jh * 4 + 0] + __ldg(&bias[col + 0]);
            r.y = acc[i][jh * 4 + 1] + __ldg(&bias[col + 1]);
            r.z = acc[i][jh * 4 + 2] + __ldg(&bias[col + 2]);
            r.w = acc[i][jh * 4 + 3] + __ldg(&bias[col + 3]);
            *(float4*)(C + (size_t)row * N + col) = r;
        }
    }
}

// ---------------------------------------------------------------------------
// Fused causal attention per (b,h) slab (contiguous [2048,128] due to the
// no-transpose reshape). Flash-style: Q block 128 rows resident, 64-key tiles,
// online softmax with floor()'d integer logits, P staged via smem for PV GEMM.
// grid = (S/128, B*H), 256 threads.
// Dynamic smem: Qs[128][129] + Ks[128][65] + Vs[64][128] + Ps[64][132]
// ---------------------------------------------------------------------------
#define QS_LD 129
#define KS_LD 65
#define PS_LD 132
#define ATTN_SMEM_FLOATS (128 * QS_LD + 128 * KS_LD + 64 * 128 + 64 * PS_LD)

__global__ __launch_bounds__(256) void attn_kernel()
{
    extern __shared__ float sm[];
    float* Qs = sm;                          // [d][i]  128 x 129
    float* Ks = Qs + 128 * QS_LD;            // [d][j]  128 x 65
    float* Vs = Ks + 128 * KS_LD;            // [j][d]  64 x 128
    float* Ps = Vs + 64 * 128;               // [j][i]  64 x 132

    const int tid = threadIdx.x;
    const int tr  = tid >> 4;    // 0..15 (row group)
    const int tc  = tid & 15;    // 0..15 (col group)
    const int qb  = blockIdx.x;  // q block 0..15
    const int bh  = blockIdx.y;  // 0..31  (= b*16 + h)

    const size_t base = (size_t)bh * (S_LEN * DKH);
    const float* qp = g_q + base + (size_t)qb * 128 * DKH;
    const float* kp0 = g_k + base;
    const float* vp0 = g_v + base;

    // Load Q block transposed: Qs[d][i]
#pragma unroll
    for (int it = 0; it < 16; it++) {
        int slot = tid + (it << 8);          // 0..4095
        int i  = slot >> 5;
        int d0 = (slot & 31) << 2;
        float4 v = *(const float4*)(qp + (size_t)i * DKH + d0);
        Qs[(d0 + 0) * QS_LD + i] = v.x;
        Qs[(d0 + 1) * QS_LD + i] = v.y;
        Qs[(d0 + 2) * QS_LD + i] = v.z;
        Qs[(d0 + 3) * QS_LD + i] = v.w;
    }

    float m_[8], l_[8], o_[8][8];
#pragma unroll
    for (int r = 0; r < 8; r++) {
        m_[r] = -INFINITY;
        l_[r] = 0.f;
#pragma unroll
        for (int c = 0; c < 8; c++) o_[r][c] = 0.f;
    }

    const int nkb = 2 * qb + 2;              // 64-key tiles (causal)
    for (int kb = 0; kb < nkb; kb++) {
        __syncthreads();   // previous iteration done with Ks/Vs/Ps (and Q ready)

        const float* kp = kp0 + (size_t)kb * 64 * DKH;
        const float* vp = vp0 + (size_t)kb * 64 * DKH;
#pragma unroll
        for (int it = 0; it < 8; it++) {
            int slot = tid + (it << 8);      // 0..2047
            int j  = slot >> 5;
            int d0 = (slot & 31) << 2;
            float4 v = *(const float4*)(kp + (size_t)j * DKH + d0);
            Ks[(d0 + 0) * KS_LD + j] = v.x;
            Ks[(d0 + 1) * KS_LD + j] = v.y;
            Ks[(d0 + 2) * KS_LD + j] = v.z;
            Ks[(d0 + 3) * KS_LD + j] = v.w;
            float4 w = *(const float4*)(vp + (size_t)j * DKH + d0);
            *(float4*)&Vs[j * 128 + d0] = w;
        }
        __syncthreads();

        // S = Q K^T  (8 rows x 4 cols per thread)
        float sacc[8][4];
#pragma unroll
        for (int r = 0; r < 8; r++)
#pragma unroll
            for (int c = 0; c < 4; c++) sacc[r][c] = 0.f;

#pragma unroll 4
        for (int d = 0; d < 128; d++) {
            const float* qr = Qs + d * QS_LD + (tr << 2);
            const float* kr = Ks + d * KS_LD + (tc << 2);
            float av[8] = {qr[0], qr[1], qr[2], qr[3],
                           qr[64], qr[65], qr[66], qr[67]};
            float bv[4] = {kr[0], kr[1], kr[2], kr[3]};
#pragma unroll
            for (int r = 0; r < 8; r++)
#pragma unroll
                for (int c = 0; c < 4; c++) sacc[r][c] += av[r] * bv[c];
        }

        // floor + causal mask + online softmax
        const int gj0 = kb * 64 + (tc << 2);
#pragma unroll
        for (int r = 0; r < 8; r++) {
            int il = (r < 4) ? ((tr << 2) + r) : (64 + (tr << 2) + r - 4);
            int gi = qb * 128 + il;
            float mrow = -INFINITY;
#pragma unroll
            for (int c = 0; c < 4; c++) {
                float s_ = floorf(sacc[r][c] / SQRT_DM);
                if (gj0 + c > gi) s_ = -INFINITY;
                sacc[r][c] = s_;
                mrow = fmaxf(mrow, s_);
            }
#pragma unroll
            for (int off = 8; off >= 1; off >>= 1)
                mrow = fmaxf(mrow, __shfl_xor_sync(0xffffffffu, mrow, off));

            float mnew = fmaxf(m_[r], mrow);
            float f = __expf(m_[r] - mnew);
            m_[r] = mnew;

            float rs = 0.f;
#pragma unroll
            for (int c = 0; c < 4; c++) {
                float p = __expf(sacc[r][c] - mnew);   // 0 for masked (-inf)
                rs += p;
                Ps[((tc << 2) + c) * PS_LD + il] = p;
            }
#pragma unroll
            for (int off = 8; off >= 1; off >>= 1)
                rs += __shfl_xor_sync(0xffffffffu, rs, off);

            l_[r] = l_[r] * f + rs;
#pragma unroll
            for (int c = 0; c < 8; c++) o_[r][c] *= f;
        }
        __syncthreads();   // Ps fully written, Vs ready

        // O += P V  (8 rows x 8 dims per thread)
#pragma unroll 2
        for (int j = 0; j < 64; j++) {
            const float* pr = Ps + j * PS_LD + (tr << 2);
            const float* vr = Vs + j * 128 + (tc << 2);
            float av[8] = {pr[0], pr[1], pr[2], pr[3],
                           pr[64], pr[65], pr[66], pr[67]};
            float bv[8] = {vr[0], vr[1], vr[2], vr[3],
                           vr[64], vr[65], vr[66], vr[67]};
#pragma unroll
            for (int r = 0; r < 8; r++)
#pragma unroll
                for (int c = 0; c < 8; c++) o_[r][c] += av[r] * bv[c];
        }
    }

    // normalize + write (contiguous slab thanks to the no-transpose reshape)
    float* op = g_o + base + (size_t)qb * 128 * DKH;
#pragma unroll
    for (int r = 0; r < 8; r++) {
        int il = (r < 4) ? ((tr << 2) + r) : (64 + (tr << 2) + r - 4);
        float inv = 1.0f / l_[r];
#pragma unroll
        for (int jh = 0; jh < 2; jh++) {
            int col = (jh ? (64 + (tc << 2)) : (tc << 2));
            float4 w;
            w.x = o_[r][jh * 4 + 0] * inv;
            w.y = o_[r][jh * 4 + 1] * inv;
            w.z = o_[r][jh * 4 + 2] * inv;
            w.w = o_[r][jh * 4 + 3] * inv;
            *(float4*)(op + (size_t)il * DKH + col) = w;
        }
    }
}

// ---------------------------------------------------------------------------
extern "C" void kernel_launch(void* const* d_in, const int* in_sizes, int n_in,
                              void* d_out, int out_size)
{
    const float* key   = (const float*)d_in[0];
    const float* query = (const float*)d_in[1];
    const float* value = (const float*)d_in[2];
    // d_in[3] = mask (causal tril, generated in-kernel instead)
    const float* Wq = (const float*)d_in[4];
    const float* bq = (const float*)d_in[5];
    const float* Wk = (const float*)d_in[6];
    const float* bk = (const float*)d_in[7];
    const float* Wv = (const float*)d_in[8];
    const float* bv = (const float*)d_in[9];
    const float* Wo = (const float*)d_in[10];
    const float* bo = (const float*)d_in[11];
    float* out = (float*)d_out;

    float *gq, *gk, *gv, *go;
    cudaGetSymbolAddress((void**)&gq, g_q);
    cudaGetSymbolAddress((void**)&gk, g_k);
    cudaGetSymbolAddress((void**)&gv, g_v);
    cudaGetSymbolAddress((void**)&go, g_o);

    dim3 gblk(DMODEL / 128, MROWS / 128);   // (16, 32)

    gemm_nt_bias<<<gblk, 256>>>(query, Wq, bq, gq);
    gemm_nt_bias<<<gblk, 256>>>(key,   Wk, bk, gk);
    gemm_nt_bias<<<gblk, 256>>>(value, Wv, bv, gv);

    const int attn_smem = ATTN_SMEM_FLOATS * (int)sizeof(float);
    cudaFuncSetAttribute(attn_kernel,
                         cudaFuncAttributeMaxDynamicSharedMemorySize, attn_smem);
    attn_kernel<<<dim3(S_LEN / 128, BATCH * NHEADS), 256, attn_smem>>>();

    gemm_nt_bias<<<gblk, 256>>>(go, Wo, bo, out);
}

// round 8
// speedup vs baseline: 1.1768x; 1.1768x over previous
#include <cuda_runtime.h>
#include <cuda_bf16.h>
#include <math.h>
#include <stdint.h>

// Problem constants
#define S_LEN 2048
#define DMODEL 2048
#define NHEADS 16
#define DKH 128
#define BATCH 2
#define MROWS (BATCH * S_LEN)   // 4096
#define SQRT_DM 45.254833995939045f

// ---------------------------------------------------------------------------
// Scratch (__device__ globals; no allocation allowed)
// ---------------------------------------------------------------------------
__device__ float g_q[(size_t)MROWS * DMODEL];
__device__ float g_k[(size_t)MROWS * DMODEL];
__device__ float g_v[(size_t)MROWS * DMODEL];
__device__ float g_o[(size_t)MROWS * DMODEL];
__device__ __nv_bfloat16 g_xh[(size_t)MROWS * DMODEL];
__device__ __nv_bfloat16 g_xl[(size_t)MROWS * DMODEL];
__device__ __nv_bfloat16 g_wh[(size_t)DMODEL * DMODEL];
__device__ __nv_bfloat16 g_wl[(size_t)DMODEL * DMODEL];

// ---------------------------------------------------------------------------
// PTX helpers (base sm_100 target safe: mma.sync / ldmatrix / cp.async only)
// ---------------------------------------------------------------------------
static __device__ __forceinline__ uint32_t smem_u32(const void* p) {
    uint32_t a;
    asm("{ .reg .u64 t; cvta.to.shared.u64 t, %1; cvt.u32.u64 %0, t; }"
        : "=r"(a) : "l"(p));
    return a;
}

#define CP_ASYNC16(saddr, gaddr) \
    asm volatile("cp.async.cg.shared.global [%0], [%1], 16;" :: "r"(saddr), "l"(gaddr))
#define CP_ASYNC_COMMIT() asm volatile("cp.async.commit_group;" ::: "memory")
#define CP_ASYNC_WAIT0()  asm volatile("cp.async.wait_group 0;" ::: "memory")
#define CP_ASYNC_WAIT1()  asm volatile("cp.async.wait_group 1;" ::: "memory")

static __device__ __forceinline__ void ldsm_x4(uint32_t (&r)[4], uint32_t addr) {
    asm volatile("ldmatrix.sync.aligned.m8n8.x4.shared.b16 {%0,%1,%2,%3}, [%4];"
                 : "=r"(r[0]), "=r"(r[1]), "=r"(r[2]), "=r"(r[3]) : "r"(addr));
}
static __device__ __forceinline__ void ldsm_x2(uint32_t (&r)[2], uint32_t addr) {
    asm volatile("ldmatrix.sync.aligned.m8n8.x2.shared.b16 {%0,%1}, [%2];"
                 : "=r"(r[0]), "=r"(r[1]) : "r"(addr));
}
static __device__ __forceinline__ void mma_bf16(float (&d)[4],
                                                const uint32_t (&a)[4],
                                                const uint32_t (&b)[2]) {
    asm volatile("mma.sync.aligned.m16n8k16.row.col.f32.bf16.bf16.f32 "
                 "{%0,%1,%2,%3}, {%4,%5,%6,%7}, {%8,%9}, {%0,%1,%2,%3};"
                 : "+f"(d[0]), "+f"(d[1]), "+f"(d[2]), "+f"(d[3])
                 : "r"(a[0]), "r"(a[1]), "r"(a[2]), "r"(a[3]),
                   "r"(b[0]), "r"(b[1]));
}

// ---------------------------------------------------------------------------
// fp32 SIMT GEMM (R1, measured-passing): C = A @ W^T + bias
// Used for the floor-critical Q/K projections.
// ---------------------------------------------------------------------------
__global__ __launch_bounds__(256) void gemm_nt_bias(
    const float* __restrict__ A, const float* __restrict__ W,
    const float* __restrict__ bias, float* __restrict__ C)
{
    const int K = DMODEL;
    const int N = DMODEL;

    __shared__ float As[16][132];
    __shared__ float Bs[16][132];

    const int tid = threadIdx.x;
    const int tr  = tid >> 4;
    const int tc  = tid & 15;
    const int bm  = blockIdx.y << 7;
    const int bn  = blockIdx.x << 7;

    const int lr = tid >> 2;
    const int lk = (tid & 3) << 2;

    const float* Ar0 = A + (size_t)(bm + lr) * K + lk;
    const float* Ar1 = A + (size_t)(bm + 64 + lr) * K + lk;
    const float* Wr0 = W + (size_t)(bn + lr) * K + lk;
    const float* Wr1 = W + (size_t)(bn + 64 + lr) * K + lk;

    float acc[8][8];
#pragma unroll
    for (int i = 0; i < 8; i++)
#pragma unroll
        for (int j = 0; j < 8; j++) acc[i][j] = 0.f;

    float4 pa0 = *(const float4*)(Ar0);
    float4 pa1 = *(const float4*)(Ar1);
    float4 pb0 = *(const float4*)(Wr0);
    float4 pb1 = *(const float4*)(Wr1);

    for (int kt = 0; kt < K; kt += 16) {
        As[lk + 0][lr] = pa0.x; As[lk + 1][lr] = pa0.y;
        As[lk + 2][lr] = pa0.z; As[lk + 3][lr] = pa0.w;
        As[lk + 0][64 + lr] = pa1.x; As[lk + 1][64 + lr] = pa1.y;
        As[lk + 2][64 + lr] = pa1.z; As[lk + 3][64 + lr] = pa1.w;
        Bs[lk + 0][lr] = pb0.x; Bs[lk + 1][lr] = pb0.y;
        Bs[lk + 2][lr] = pb0.z; Bs[lk + 3][lr] = pb0.w;
        Bs[lk + 0][64 + lr] = pb1.x; Bs[lk + 1][64 + lr] = pb1.y;
        Bs[lk + 2][64 + lr] = pb1.z; Bs[lk + 3][64 + lr] = pb1.w;
        __syncthreads();

        if (kt + 16 < K) {
            pa0 = *(const float4*)(Ar0 + kt + 16);
            pa1 = *(const float4*)(Ar1 + kt + 16);
            pb0 = *(const float4*)(Wr0 + kt + 16);
            pb1 = *(const float4*)(Wr1 + kt + 16);
        }

#pragma unroll
        for (int k = 0; k < 16; k++) {
            float4 x0 = *(const float4*)&As[k][tr << 2];
            float4 x1 = *(const float4*)&As[k][64 + (tr << 2)];
            float4 y0 = *(const float4*)&Bs[k][tc << 2];
            float4 y1 = *(const float4*)&Bs[k][64 + (tc << 2)];
            float av[8] = {x0.x, x0.y, x0.z, x0.w, x1.x, x1.y, x1.z, x1.w};
            float bv[8] = {y0.x, y0.y, y0.z, y0.w, y1.x, y1.y, y1.z, y1.w};
#pragma unroll
            for (int i = 0; i < 8; i++)
#pragma unroll
                for (int j = 0; j < 8; j++) acc[i][j] += av[i] * bv[j];
        }
        __syncthreads();
    }

#pragma unroll
    for (int i = 0; i < 8; i++) {
        int row = bm + ((i < 4) ? ((tr << 2) + i) : (64 + (tr << 2) + i - 4));
#pragma unroll
        for (int jh = 0; jh < 2; jh++) {
            int col = bn + (jh ? (64 + (tc << 2)) : (tc << 2));
            float4 r;
            r.x = acc[i][jh * 4 + 0] + __ldg(&bias[col + 0]);
            r.y = acc[i][jh * 4 + 1] + __ldg(&bias[col + 1]);
            r.z = acc[i][jh * 4 + 2] + __ldg(&bias[col + 2]);
            r.w = acc[i][jh * 4 + 3] + __ldg(&bias[col + 3]);
            *(float4*)(C + (size_t)row * N + col) = r;
        }
    }
}

// ---------------------------------------------------------------------------
// Split fp32 -> (bf16 hi, bf16 lo); residual exact in fp32.
// ---------------------------------------------------------------------------
__global__ __launch_bounds__(256) void split2_bf16(
    const float* __restrict__ x,
    __nv_bfloat16* __restrict__ h, __nv_bfloat16* __restrict__ l, int n4)
{
    int i = blockIdx.x * blockDim.x + threadIdx.x;
    if (i >= n4) return;
    float4 v = ((const float4*)x)[i];
    float vv[4] = {v.x, v.y, v.z, v.w};
    __nv_bfloat16 hh[4], ll[4];
#pragma unroll
    for (int j = 0; j < 4; j++) {
        hh[j] = __float2bfloat16(vv[j]);
        ll[j] = __float2bfloat16(vv[j] - __bfloat162float(hh[j]));
    }
    __nv_bfloat162* hp = (__nv_bfloat162*)h + 2 * (size_t)i;
    __nv_bfloat162* lp = (__nv_bfloat162*)l + 2 * (size_t)i;
    hp[0] = __halves2bfloat162(hh[0], hh[1]);
    hp[1] = __halves2bfloat162(hh[2], hh[3]);
    lp[0] = __halves2bfloat162(ll[0], ll[1]);
    lp[1] = __halves2bfloat162(ll[2], ll[3]);
}

// ---------------------------------------------------------------------------
// mma.sync bf16x3 GEMM (hh + hl + lh) with per-K-chunk drained accumulation.
// Smooth paths only (V and O projections). Block 128x128, Kc=32, 8 warps.
// ---------------------------------------------------------------------------
#define GB_BM 128
#define GB_BN 128
#define GB_BK 32
#define LDP 40
#define TILE_ELEMS (128 * LDP)            // 5120 halves
#define STG_BYTES (4 * TILE_ELEMS * 2)    // Ah, Al, Bh, Bl per stage
#define GEMM_SMEM (2 * STG_BYTES)         // 81920 B
#define NCHUNK (DMODEL / GB_BK)           // 64

__global__ __launch_bounds__(256) void gemm_bf16x3(
    const __nv_bfloat16* __restrict__ Ah, const __nv_bfloat16* __restrict__ Al,
    const __nv_bfloat16* __restrict__ Bh, const __nv_bfloat16* __restrict__ Bl,
    const float* __restrict__ bias, float* __restrict__ C)
{
    extern __shared__ __nv_bfloat16 smem[];
    const uint32_t sbase = smem_u32(smem);

    const int tid  = threadIdx.x;
    const int wid  = tid >> 5;
    const int lane = tid & 31;
    const int wm   = wid & 1;
    const int wn   = wid >> 1;
    const int bm   = blockIdx.y * GB_BM;
    const int bn   = blockIdx.x * GB_BN;

    float sum[4][4][4];
#pragma unroll
    for (int m = 0; m < 4; m++)
#pragma unroll
        for (int n = 0; n < 4; n++)
#pragma unroll
            for (int e = 0; e < 4; e++) sum[m][n][e] = 0.f;

    const int li0 = tid * 2;

    auto prefetch = [&](int chunk) {
        const uint32_t st = sbase + (uint32_t)(chunk & 1) * STG_BYTES;
        const int kk = chunk * GB_BK;
#pragma unroll
        for (int i = 0; i < 2; i++) {
            int idx = li0 + i;
            int r = idx >> 2;
            int c = (idx & 3) * 8;
            uint32_t soff = (uint32_t)(r * LDP + c) * 2;
            size_t ga = (size_t)(bm + r) * DMODEL + kk + c;
            size_t gb = (size_t)(bn + r) * DMODEL + kk + c;
            CP_ASYNC16(st + soff, Ah + ga);
            CP_ASYNC16(st + (uint32_t)TILE_ELEMS * 2 + soff, Al + ga);
            CP_ASYNC16(st + (uint32_t)(2 * TILE_ELEMS) * 2 + soff, Bh + gb);
            CP_ASYNC16(st + (uint32_t)(3 * TILE_ELEMS) * 2 + soff, Bl + gb);
        }
    };

    prefetch(0);
    CP_ASYNC_COMMIT();

    const int a_row = wm * 64 + (lane & 15);
    const int a_colh = (lane >> 4) * 8;
    const int b_row = wn * 32 + (lane & 7);
    const int b_colh = ((lane >> 3) & 1) * 8;

    for (int chunk = 0; chunk < NCHUNK; chunk++) {
        if (chunk + 1 < NCHUNK) {
            prefetch(chunk + 1);
            CP_ASYNC_COMMIT();
            CP_ASYNC_WAIT1();
        } else {
            CP_ASYNC_WAIT0();
        }
        __syncthreads();

        const uint32_t st = sbase + (uint32_t)(chunk & 1) * STG_BYTES;

        // fresh per-chunk fragment accumulator (drain target)
        float cacc[4][4][4];
#pragma unroll
        for (int m = 0; m < 4; m++)
#pragma unroll
            for (int n = 0; n < 4; n++)
#pragma unroll
                for (int e = 0; e < 4; e++) cacc[m][n][e] = 0.f;

#pragma unroll
        for (int ks = 0; ks < GB_BK; ks += 16) {
            uint32_t ah[4][4], al[4][4], bh[4][2], bl[4][2];
#pragma unroll
            for (int m = 0; m < 4; m++) {
                uint32_t off = (uint32_t)((a_row + m * 16) * LDP + ks + a_colh) * 2;
                ldsm_x4(ah[m], st + off);
                ldsm_x4(al[m], st + (uint32_t)TILE_ELEMS * 2 + off);
            }
#pragma unroll
            for (int n = 0; n < 4; n++) {
                uint32_t off = (uint32_t)((b_row + n * 8) * LDP + ks + b_colh) * 2;
                ldsm_x2(bh[n], st + (uint32_t)(2 * TILE_ELEMS) * 2 + off);
                ldsm_x2(bl[n], st + (uint32_t)(3 * TILE_ELEMS) * 2 + off);
            }
#pragma unroll
            for (int m = 0; m < 4; m++)
#pragma unroll
                for (int n = 0; n < 4; n++) {
                    mma_bf16(cacc[m][n], ah[m], bh[n]);
                    mma_bf16(cacc[m][n], ah[m], bl[n]);
                    mma_bf16(cacc[m][n], al[m], bh[n]);
                }
        }

        // drain: RN fp32 fold into persistent sum
#pragma unroll
        for (int m = 0; m < 4; m++)
#pragma unroll
            for (int n = 0; n < 4; n++)
#pragma unroll
                for (int e = 0; e < 4; e++) sum[m][n][e] += cacc[m][n][e];

        __syncthreads();
    }

#pragma unroll
    for (int m = 0; m < 4; m++) {
        int row0 = bm + wm * 64 + m * 16 + (lane >> 2);
#pragma unroll
        for (int n = 0; n < 4; n++) {
            int col = bn + wn * 32 + n * 8 + (lane & 3) * 2;
            float2 bb = __ldg((const float2*)&bias[col]);
            float2 w0 = {sum[m][n][0] + bb.x, sum[m][n][1] + bb.y};
            float2 w1 = {sum[m][n][2] + bb.x, sum[m][n][3] + bb.y};
            *(float2*)(C + (size_t)row0 * DMODEL + col) = w0;
            *(float2*)(C + (size_t)(row0 + 8) * DMODEL + col) = w1;
        }
    }
}

// ---------------------------------------------------------------------------
// Fused causal attention (fp32 SIMT flash-style) — unchanged, measured-good.
// ---------------------------------------------------------------------------
#define QS_LD 129
#define KS_LD 65
#define PS_LD 132
#define ATTN_SMEM_FLOATS (128 * QS_LD + 128 * KS_LD + 64 * 128 + 64 * PS_LD)

__global__ __launch_bounds__(256) void attn_kernel()
{
    extern __shared__ float sm[];
    float* Qs = sm;
    float* Ks = Qs + 128 * QS_LD;
    float* Vs = Ks + 128 * KS_LD;
    float* Ps = Vs + 64 * 128;

    const int tid = threadIdx.x;
    const int tr  = tid >> 4;
    const int tc  = tid & 15;
    const int qb  = blockIdx.x;
    const int bh  = blockIdx.y;

    const size_t base = (size_t)bh * (S_LEN * DKH);
    const float* qp = g_q + base + (size_t)qb * 128 * DKH;
    const float* kp0 = g_k + base;
    const float* vp0 = g_v + base;

#pragma unroll
    for (int it = 0; it < 16; it++) {
        int slot = tid + (it << 8);
        int i  = slot >> 5;
        int d0 = (slot & 31) << 2;
        float4 v = *(const float4*)(qp + (size_t)i * DKH + d0);
        Qs[(d0 + 0) * QS_LD + i] = v.x;
        Qs[(d0 + 1) * QS_LD + i] = v.y;
        Qs[(d0 + 2) * QS_LD + i] = v.z;
        Qs[(d0 + 3) * QS_LD + i] = v.w;
    }

    float m_[8], l_[8], o_[8][8];
#pragma unroll
    for (int r = 0; r < 8; r++) {
        m_[r] = -INFINITY;
        l_[r] = 0.f;
#pragma unroll
        for (int c = 0; c < 8; c++) o_[r][c] = 0.f;
    }

    const int nkb = 2 * qb + 2;
    for (int kb = 0; kb < nkb; kb++) {
        __syncthreads();

        const float* kp = kp0 + (size_t)kb * 64 * DKH;
        const float* vp = vp0 + (size_t)kb * 64 * DKH;
#pragma unroll
        for (int it = 0; it < 8; it++) {
            int slot = tid + (it << 8);
            int j  = slot >> 5;
            int d0 = (slot & 31) << 2;
            float4 v = *(const float4*)(kp + (size_t)j * DKH + d0);
            Ks[(d0 + 0) * KS_LD + j] = v.x;
            Ks[(d0 + 1) * KS_LD + j] = v.y;
            Ks[(d0 + 2) * KS_LD + j] = v.z;
            Ks[(d0 + 3) * KS_LD + j] = v.w;
            float4 w = *(const float4*)(vp + (size_t)j * DKH + d0);
            *(float4*)&Vs[j * 128 + d0] = w;
        }
        __syncthreads();

        float sacc[8][4];
#pragma unroll
        for (int r = 0; r < 8; r++)
#pragma unroll
            for (int c = 0; c < 4; c++) sacc[r][c] = 0.f;

#pragma unroll 4
        for (int d = 0; d < 128; d++) {
            const float* qr = Qs + d * QS_LD + (tr << 2);
            const float* kr = Ks + d * KS_LD + (tc << 2);
            float av[8] = {qr[0], qr[1], qr[2], qr[3],
                           qr[64], qr[65], qr[66], qr[67]};
            float bv[4] = {kr[0], kr[1], kr[2], kr[3]};
#pragma unroll
            for (int r = 0; r < 8; r++)
#pragma unroll
                for (int c = 0; c < 4; c++) sacc[r][c] += av[r] * bv[c];
        }

        const int gj0 = kb * 64 + (tc << 2);
#pragma unroll
        for (int r = 0; r < 8; r++) {
            int il = (r < 4) ? ((tr << 2) + r) : (64 + (tr << 2) + r - 4);
            int gi = qb * 128 + il;
            float mrow = -INFINITY;
#pragma unroll
            for (int c = 0; c < 4; c++) {
                float s_ = floorf(sacc[r][c] / SQRT_DM);
                if (gj0 + c > gi) s_ = -INFINITY;
                sacc[r][c] = s_;
                mrow = fmaxf(mrow, s_);
            }
#pragma unroll
            for (int off = 8; off >= 1; off >>= 1)
                mrow = fmaxf(mrow, __shfl_xor_sync(0xffffffffu, mrow, off));

            float mnew = fmaxf(m_[r], mrow);
            float f = __expf(m_[r] - mnew);
            m_[r] = mnew;

            float rs = 0.f;
#pragma unroll
            for (int c = 0; c < 4; c++) {
                float p = __expf(sacc[r][c] - mnew);
                rs += p;
                Ps[((tc << 2) + c) * PS_LD + il] = p;
            }
#pragma unroll
            for (int off = 8; off >= 1; off >>= 1)
                rs += __shfl_xor_sync(0xffffffffu, rs, off);

            l_[r] = l_[r] * f + rs;
#pragma unroll
            for (int c = 0; c < 8; c++) o_[r][c] *= f;
        }
        __syncthreads();

#pragma unroll 2
        for (int j = 0; j < 64; j++) {
            const float* pr = Ps + j * PS_LD + (tr << 2);
            const float* vr = Vs + j * 128 + (tc << 2);
            float av[8] = {pr[0], pr[1], pr[2], pr[3],
                           pr[64], pr[65], pr[66], pr[67]};
            float bv[8] = {vr[0], vr[1], vr[2], vr[3],
                           vr[64], vr[65], vr[66], vr[67]};
#pragma unroll
            for (int r = 0; r < 8; r++)
#pragma unroll
                for (int c = 0; c < 8; c++) o_[r][c] += av[r] * bv[c];
        }
    }

    float* op = g_o + base + (size_t)qb * 128 * DKH;
#pragma unroll
    for (int r = 0; r < 8; r++) {
        int il = (r < 4) ? ((tr << 2) + r) : (64 + (tr << 2) + r - 4);
        float inv = 1.0f / l_[r];
#pragma unroll
        for (int jh = 0; jh < 2; jh++) {
            int col = (jh ? (64 + (tc << 2)) : (tc << 2));
            float4 w;
            w.x = o_[r][jh * 4 + 0] * inv;
            w.y = o_[r][jh * 4 + 1] * inv;
            w.z = o_[r][jh * 4 + 2] * inv;
            w.w = o_[r][jh * 4 + 3] * inv;
            *(float4*)(op + (size_t)il * DKH + col) = w;
        }
    }
}

// ---------------------------------------------------------------------------
extern "C" void kernel_launch(void* const* d_in, const int* in_sizes, int n_in,
                              void* d_out, int out_size)
{
    const float* key   = (const float*)d_in[0];
    const float* query = (const float*)d_in[1];
    const float* value = (const float*)d_in[2];
    const float* Wq = (const float*)d_in[4];
    const float* bq = (const float*)d_in[5];
    const float* Wk = (const float*)d_in[6];
    const float* bk = (const float*)d_in[7];
    const float* Wv = (const float*)d_in[8];
    const float* bv = (const float*)d_in[9];
    const float* Wo = (const float*)d_in[10];
    const float* bo = (const float*)d_in[11];
    float* out = (float*)d_out;

    float *gq, *gk, *gv, *go;
    __nv_bfloat16 *xh, *xl, *wh, *wl;
    cudaGetSymbolAddress((void**)&gq, g_q);
    cudaGetSymbolAddress((void**)&gk, g_k);
    cudaGetSymbolAddress((void**)&gv, g_v);
    cudaGetSymbolAddress((void**)&go, g_o);
    cudaGetSymbolAddress((void**)&xh, g_xh);
    cudaGetSymbolAddress((void**)&xl, g_xl);
    cudaGetSymbolAddress((void**)&wh, g_wh);
    cudaGetSymbolAddress((void**)&wl, g_wl);

    cudaFuncSetAttribute(gemm_bf16x3,
                         cudaFuncAttributeMaxDynamicSharedMemorySize, GEMM_SMEM);
    const int attn_smem = ATTN_SMEM_FLOATS * (int)sizeof(float);
    cudaFuncSetAttribute(attn_kernel,
                         cudaFuncAttributeMaxDynamicSharedMemorySize, attn_smem);

    const int nx4 = MROWS * DMODEL / 4;
    const int nw4 = DMODEL * DMODEL / 4;
    dim3 gfp32(DMODEL / 128, MROWS / 128);       // (16, 32)
    dim3 gmma(DMODEL / GB_BN, MROWS / GB_BM);    // (16, 32)

    // Q/K projections: floor-critical -> fp32 SIMT (R1-identical numerics)
    gemm_nt_bias<<<gfp32, 256>>>(query, Wq, bq, gq);
    gemm_nt_bias<<<gfp32, 256>>>(key,   Wk, bk, gk);

    // V projection: smooth -> bf16x3 mma with drained accumulation
    split2_bf16<<<nx4 / 256, 256>>>(value, xh, xl, nx4);
    split2_bf16<<<nw4 / 256, 256>>>(Wv, wh, wl, nw4);
    gemm_bf16x3<<<gmma, 256, GEMM_SMEM>>>(xh, xl, wh, wl, bv, gv);

    // Attention (fp32, unchanged)
    attn_kernel<<<dim3(S_LEN / 128, BATCH * NHEADS), 256, attn_smem>>>();

    // Output projection: smooth -> bf16x3 mma with drained accumulation
    split2_bf16<<<nx4 / 256, 256>>>(go, xh, xl, nx4);
    split2_bf16<<<nw4 / 256, 256>>>(Wo, wh, wl, nw4);
    gemm_bf16x3<<<gmma, 256, GEMM_SMEM>>>(xh, xl, wh, wl, bo, out);
}

// round 10
// speedup vs baseline: 1.2283x; 1.0437x over previous
#include <cuda_runtime.h>
#include <cuda_bf16.h>
#include <math.h>
#include <stdint.h>

// Problem constants
#define S_LEN 2048
#define DMODEL 2048
#define NHEADS 16
#define DKH 128
#define BATCH 2
#define MROWS (BATCH * S_LEN)   // 4096
#define SQRT_DM 45.254833995939045f

// ---------------------------------------------------------------------------
// Scratch (__device__ globals; no allocation allowed)
// ---------------------------------------------------------------------------
__device__ float g_q[(size_t)MROWS * DMODEL];
__device__ float g_k[(size_t)MROWS * DMODEL];
__device__ float g_v[(size_t)MROWS * DMODEL];
__device__ float g_o[(size_t)MROWS * DMODEL];
__device__ __nv_bfloat16 g_xh[(size_t)MROWS * DMODEL];
__device__ __nv_bfloat16 g_xl[(size_t)MROWS * DMODEL];
__device__ __nv_bfloat16 g_wh[(size_t)DMODEL * DMODEL];
__device__ __nv_bfloat16 g_wl[(size_t)DMODEL * DMODEL];

// ---------------------------------------------------------------------------
// PTX helpers (base sm_100 target safe: mma.sync / ldmatrix / cp.async only)
// ---------------------------------------------------------------------------
static __device__ __forceinline__ uint32_t smem_u32(const void* p) {
    uint32_t a;
    asm("{ .reg .u64 t; cvta.to.shared.u64 t, %1; cvt.u32.u64 %0, t; }"
        : "=r"(a) : "l"(p));
    return a;
}

#define CP_ASYNC16(saddr, gaddr) \
    asm volatile("cp.async.cg.shared.global [%0], [%1], 16;" :: "r"(saddr), "l"(gaddr))
#define CP_ASYNC_COMMIT() asm volatile("cp.async.commit_group;" ::: "memory")
#define CP_ASYNC_WAIT0()  asm volatile("cp.async.wait_group 0;" ::: "memory")
#define CP_ASYNC_WAIT1()  asm volatile("cp.async.wait_group 1;" ::: "memory")

static __device__ __forceinline__ void ldsm_x4(uint32_t (&r)[4], uint32_t addr) {
    asm volatile("ldmatrix.sync.aligned.m8n8.x4.shared.b16 {%0,%1,%2,%3}, [%4];"
                 : "=r"(r[0]), "=r"(r[1]), "=r"(r[2]), "=r"(r[3]) : "r"(addr));
}
static __device__ __forceinline__ void mma_bf16(float (&d)[4],
                                                const uint32_t (&a)[4],
                                                const uint32_t b0, const uint32_t b1) {
    asm volatile("mma.sync.aligned.m16n8k16.row.col.f32.bf16.bf16.f32 "
                 "{%0,%1,%2,%3}, {%4,%5,%6,%7}, {%8,%9}, {%0,%1,%2,%3};"
                 : "+f"(d[0]), "+f"(d[1]), "+f"(d[2]), "+f"(d[3])
                 : "r"(a[0]), "r"(a[1]), "r"(a[2]), "r"(a[3]),
                   "r"(b0), "r"(b1));
}

// ---------------------------------------------------------------------------
// fp32 SIMT GEMM (R1, measured-passing): C = A @ W^T + bias
// Used for the floor-critical Q/K projections. UNCHANGED numerics.
// ---------------------------------------------------------------------------
__global__ __launch_bounds__(256) void gemm_nt_bias(
    const float* __restrict__ A, const float* __restrict__ W,
    const float* __restrict__ bias, float* __restrict__ C)
{
    const int K = DMODEL;
    const int N = DMODEL;

    __shared__ float As[16][132];
    __shared__ float Bs[16][132];

    const int tid = threadIdx.x;
    const int tr  = tid >> 4;
    const int tc  = tid & 15;
    const int bm  = blockIdx.y << 7;
    const int bn  = blockIdx.x << 7;

    const int lr = tid >> 2;
    const int lk = (tid & 3) << 2;

    const float* Ar0 = A + (size_t)(bm + lr) * K + lk;
    const float* Ar1 = A + (size_t)(bm + 64 + lr) * K + lk;
    const float* Wr0 = W + (size_t)(bn + lr) * K + lk;
    const float* Wr1 = W + (size_t)(bn + 64 + lr) * K + lk;

    float acc[8][8];
#pragma unroll
    for (int i = 0; i < 8; i++)
#pragma unroll
        for (int j = 0; j < 8; j++) acc[i][j] = 0.f;

    float4 pa0 = *(const float4*)(Ar0);
    float4 pa1 = *(const float4*)(Ar1);
    float4 pb0 = *(const float4*)(Wr0);
    float4 pb1 = *(const float4*)(Wr1);

    for (int kt = 0; kt < K; kt += 16) {
        As[lk + 0][lr] = pa0.x; As[lk + 1][lr] = pa0.y;
        As[lk + 2][lr] = pa0.z; As[lk + 3][lr] = pa0.w;
        As[lk + 0][64 + lr] = pa1.x; As[lk + 1][64 + lr] = pa1.y;
        As[lk + 2][64 + lr] = pa1.z; As[lk + 3][64 + lr] = pa1.w;
        Bs[lk + 0][lr] = pb0.x; Bs[lk + 1][lr] = pb0.y;
        Bs[lk + 2][lr] = pb0.z; Bs[lk + 3][lr] = pb0.w;
        Bs[lk + 0][64 + lr] = pb1.x; Bs[lk + 1][64 + lr] = pb1.y;
        Bs[lk + 2][64 + lr] = pb1.z; Bs[lk + 3][64 + lr] = pb1.w;
        __syncthreads();

        if (kt + 16 < K) {
            pa0 = *(const float4*)(Ar0 + kt + 16);
            pa1 = *(const float4*)(Ar1 + kt + 16);
            pb0 = *(const float4*)(Wr0 + kt + 16);
            pb1 = *(const float4*)(Wr1 + kt + 16);
        }

#pragma unroll
        for (int k = 0; k < 16; k++) {
            float4 x0 = *(const float4*)&As[k][tr << 2];
            float4 x1 = *(const float4*)&As[k][64 + (tr << 2)];
            float4 y0 = *(const float4*)&Bs[k][tc << 2];
            float4 y1 = *(const float4*)&Bs[k][64 + (tc << 2)];
            float av[8] = {x0.x, x0.y, x0.z, x0.w, x1.x, x1.y, x1.z, x1.w};
            float bv[8] = {y0.x, y0.y, y0.z, y0.w, y1.x, y1.y, y1.z, y1.w};
#pragma unroll
            for (int i = 0; i < 8; i++)
#pragma unroll
                for (int j = 0; j < 8; j++) acc[i][j] += av[i] * bv[j];
        }
        __syncthreads();
    }

#pragma unroll
    for (int i = 0; i < 8; i++) {
        int row = bm + ((i < 4) ? ((tr << 2) + i) : (64 + (tr << 2) + i - 4));
#pragma unroll
        for (int jh = 0; jh < 2; jh++) {
            int col = bn + (jh ? (64 + (tc << 2)) : (tc << 2));
            float4 r;
            r.x = acc[i][jh * 4 + 0] + __ldg(&bias[col + 0]);
            r.y = acc[i][jh * 4 + 1] + __ldg(&bias[col + 1]);
            r.z = acc[i][jh * 4 + 2] + __ldg(&bias[col + 2]);
            r.w = acc[i][jh * 4 + 3] + __ldg(&bias[col + 3]);
            *(float4*)(C + (size_t)row * N + col) = r;
        }
    }
}

// ---------------------------------------------------------------------------
// Split fp32 -> (bf16 hi, bf16 lo); residual exact in fp32.
// ---------------------------------------------------------------------------
__global__ __launch_bounds__(256) void split2_bf16(
    const float* __restrict__ x,
    __nv_bfloat16* __restrict__ h, __nv_bfloat16* __restrict__ l, int n4)
{
    int i = blockIdx.x * blockDim.x + threadIdx.x;
    if (i >= n4) return;
    float4 v = ((const float4*)x)[i];
    float vv[4] = {v.x, v.y, v.z, v.w};
    __nv_bfloat16 hh[4], ll[4];
#pragma unroll
    for (int j = 0; j < 4; j++) {
        hh[j] = __float2bfloat16(vv[j]);
        ll[j] = __float2bfloat16(vv[j] - __bfloat162float(hh[j]));
    }
    __nv_bfloat162* hp = (__nv_bfloat162*)h + 2 * (size_t)i;
    __nv_bfloat162* lp = (__nv_bfloat162*)l + 2 * (size_t)i;
    hp[0] = __halves2bfloat162(hh[0], hh[1]);
    hp[1] = __halves2bfloat162(hh[2], hh[3]);
    lp[0] = __halves2bfloat162(ll[0], ll[1]);
    lp[1] = __halves2bfloat162(ll[2], ll[3]);
}

// ---------------------------------------------------------------------------
// mma.sync bf16x3 GEMM (hh + hl + lh), DIRECT accumulation (smooth paths).
// v2: __launch_bounds__(256,2) for 2 CTAs/SM, paired-x4 B-fragment loads.
// Block 128x128, Kc=32, 8 warps (warp tile 64x32), 2-stage cp.async.
// ---------------------------------------------------------------------------
#define GB_BM 128
#define GB_BN 128
#define GB_BK 32
#define LDP 40
#define TILE_ELEMS (128 * LDP)            // 5120 halves
#define STG_BYTES (4 * TILE_ELEMS * 2)    // Ah, Al, Bh, Bl per stage
#define GEMM_SMEM (2 * STG_BYTES)         // 81920 B -> 2 CTAs/SM
#define NCHUNK (DMODEL / GB_BK)           // 64

__global__ __launch_bounds__(256, 2) void gemm_bf16x3(
    const __nv_bfloat16* __restrict__ Ah, const __nv_bfloat16* __restrict__ Al,
    const __nv_bfloat16* __restrict__ Bh, const __nv_bfloat16* __restrict__ Bl,
    const float* __restrict__ bias, float* __restrict__ C)
{
    extern __shared__ __nv_bfloat16 smem[];
    const uint32_t sbase = smem_u32(smem);

    const int tid  = threadIdx.x;
    const int wid  = tid >> 5;
    const int lane = tid & 31;
    const int wm   = wid & 1;
    const int wn   = wid >> 1;
    const int bm   = blockIdx.y * GB_BM;
    const int bn   = blockIdx.x * GB_BN;

    float sum[4][4][4];
#pragma unroll
    for (int m = 0; m < 4; m++)
#pragma unroll
        for (int n = 0; n < 4; n++)
#pragma unroll
            for (int e = 0; e < 4; e++) sum[m][n][e] = 0.f;

    const int li0 = tid * 2;

    auto prefetch = [&](int chunk) {
        const uint32_t st = sbase + (uint32_t)(chunk & 1) * STG_BYTES;
        const int kk = chunk * GB_BK;
#pragma unroll
        for (int i = 0; i < 2; i++) {
            int idx = li0 + i;
            int r = idx >> 2;
            int c = (idx & 3) * 8;
            uint32_t soff = (uint32_t)(r * LDP + c) * 2;
            size_t ga = (size_t)(bm + r) * DMODEL + kk + c;
            size_t gb = (size_t)(bn + r) * DMODEL + kk + c;
            CP_ASYNC16(st + soff, Ah + ga);
            CP_ASYNC16(st + (uint32_t)TILE_ELEMS * 2 + soff, Al + ga);
            CP_ASYNC16(st + (uint32_t)(2 * TILE_ELEMS) * 2 + soff, Bh + gb);
            CP_ASYNC16(st + (uint32_t)(3 * TILE_ELEMS) * 2 + soff, Bl + gb);
        }
    };

    prefetch(0);
    CP_ASYNC_COMMIT();

    // A-fragment lane address (x4: m16 x k16 per m-tile)
    const int a_row = wm * 64 + (lane & 15);
    const int a_colh = (lane >> 4) * 8;
    // B-fragment PAIRED x4 lane address: two n8-tiles per ldmatrix.x4.
    // lanes 0-7: tile0 rows @k0; 8-15: tile0 @k8; 16-23: tile1 @k0; 24-31: tile1 @k8
    const int bp_row = wn * 32 + ((lane >> 4) & 1) * 8 + (lane & 7);
    const int bp_colh = ((lane >> 3) & 1) * 8;

    for (int chunk = 0; chunk < NCHUNK; chunk++) {
        if (chunk + 1 < NCHUNK) {
            prefetch(chunk + 1);
            CP_ASYNC_COMMIT();
            CP_ASYNC_WAIT1();
        } else {
            CP_ASYNC_WAIT0();
        }
        __syncthreads();

        const uint32_t st = sbase + (uint32_t)(chunk & 1) * STG_BYTES;

#pragma unroll
        for (int ks = 0; ks < GB_BK; ks += 16) {
            uint32_t ah[4][4], al[4][4], bh[4][2], bl[4][2];
#pragma unroll
            for (int m = 0; m < 4; m++) {
                uint32_t off = (uint32_t)((a_row + m * 16) * LDP + ks + a_colh) * 2;
                ldsm_x4(ah[m], st + off);
                ldsm_x4(al[m], st + (uint32_t)TILE_ELEMS * 2 + off);
            }
#pragma unroll
            for (int np = 0; np < 2; np++) {   // n-tile pairs (2np, 2np+1)
                uint32_t off = (uint32_t)((bp_row + np * 16) * LDP + ks + bp_colh) * 2;
                uint32_t rh[4], rl[4];
                ldsm_x4(rh, st + (uint32_t)(2 * TILE_ELEMS) * 2 + off);
                ldsm_x4(rl, st + (uint32_t)(3 * TILE_ELEMS) * 2 + off);
                bh[2 * np + 0][0] = rh[0]; bh[2 * np + 0][1] = rh[1];
                bh[2 * np + 1][0] = rh[2]; bh[2 * np + 1][1] = rh[3];
                bl[2 * np + 0][0] = rl[0]; bl[2 * np + 0][1] = rl[1];
                bl[2 * np + 1][0] = rl[2]; bl[2 * np + 1][1] = rl[3];
            }
#pragma unroll
            for (int m = 0; m < 4; m++)
#pragma unroll
                for (int n = 0; n < 4; n++) {
                    mma_bf16(sum[m][n], ah[m], bh[n][0], bh[n][1]);
                    mma_bf16(sum[m][n], ah[m], bl[n][0], bl[n][1]);
                    mma_bf16(sum[m][n], al[m], bh[n][0], bh[n][1]);
                }
        }
        __syncthreads();
    }

#pragma unroll
    for (int m = 0; m < 4; m++) {
        int row0 = bm + wm * 64 + m * 16 + (lane >> 2);
#pragma unroll
        for (int n = 0; n < 4; n++) {
            int col = bn + wn * 32 + n * 8 + (lane & 3) * 2;
            float2 bb = __ldg((const float2*)&bias[col]);
            float2 w0 = {sum[m][n][0] + bb.x, sum[m][n][1] + bb.y};
            float2 w1 = {sum[m][n][2] + bb.x, sum[m][n][3] + bb.y};
            *(float2*)(C + (size_t)row0 * DMODEL + col) = w0;
            *(float2*)(C + (size_t)(row0 + 8) * DMODEL + col) = w1;
        }
    }
}

// ---------------------------------------------------------------------------
// Fused causal attention (fp32 SIMT flash-style) — unchanged, measured-good.
// ---------------------------------------------------------------------------
#define QS_LD 129
#define KS_LD 65
#define PS_LD 132
#define ATTN_SMEM_FLOATS (128 * QS_LD + 128 * KS_LD + 64 * 128 + 64 * PS_LD)

__global__ __launch_bounds__(256) void attn_kernel()
{
    extern __shared__ float sm[];
    float* Qs = sm;
    float* Ks = Qs + 128 * QS_LD;
    float* Vs = Ks + 128 * KS_LD;
    float* Ps = Vs + 64 * 128;

    const int tid = threadIdx.x;
    const int tr  = tid >> 4;
    const int tc  = tid & 15;
    const int qb  = blockIdx.x;
    const int bh  = blockIdx.y;

    const size_t base = (size_t)bh * (S_LEN * DKH);
    const float* qp = g_q + base + (size_t)qb * 128 * DKH;
    const float* kp0 = g_k + base;
    const float* vp0 = g_v + base;

#pragma unroll
    for (int it = 0; it < 16; it++) {
        int slot = tid + (it << 8);
        int i  = slot >> 5;
        int d0 = (slot & 31) << 2;
        float4 v = *(const float4*)(qp + (size_t)i * DKH + d0);
        Qs[(d0 + 0) * QS_LD + i] = v.x;
        Qs[(d0 + 1) * QS_LD + i] = v.y;
        Qs[(d0 + 2) * QS_LD + i] = v.z;
        Qs[(d0 + 3) * QS_LD + i] = v.w;
    }

    float m_[8], l_[8], o_[8][8];
#pragma unroll
    for (int r = 0; r < 8; r++) {
        m_[r] = -INFINITY;
        l_[r] = 0.f;
#pragma unroll
        for (int c = 0; c < 8; c++) o_[r][c] = 0.f;
    }

    const int nkb = 2 * qb + 2;
    for (int kb = 0; kb < nkb; kb++) {
        __syncthreads();

        const float* kp = kp0 + (size_t)kb * 64 * DKH;
        const float* vp = vp0 + (size_t)kb * 64 * DKH;
#pragma unroll
        for (int it = 0; it < 8; it++) {
            int slot = tid + (it << 8);
            int j  = slot >> 5;
            int d0 = (slot & 31) << 2;
            float4 v = *(const float4*)(kp + (size_t)j * DKH + d0);
            Ks[(d0 + 0) * KS_LD + j] = v.x;
            Ks[(d0 + 1) * KS_LD + j] = v.y;
            Ks[(d0 + 2) * KS_LD + j] = v.z;
            Ks[(d0 + 3) * KS_LD + j] = v.w;
            float4 w = *(const float4*)(vp + (size_t)j * DKH + d0);
            *(float4*)&Vs[j * 128 + d0] = w;
        }
        __syncthreads();

        float sacc[8][4];
#pragma unroll
        for (int r = 0; r < 8; r++)
#pragma unroll
            for (int c = 0; c < 4; c++) sacc[r][c] = 0.f;

#pragma unroll 4
        for (int d = 0; d < 128; d++) {
            const float* qr = Qs + d * QS_LD + (tr << 2);
            const float* kr = Ks + d * KS_LD + (tc << 2);
            float av[8] = {qr[0], qr[1], qr[2], qr[3],
                           qr[64], qr[65], qr[66], qr[67]};
            float bv[4] = {kr[0], kr[1], kr[2], kr[3]};
#pragma unroll
            for (int r = 0; r < 8; r++)
#pragma unroll
                for (int c = 0; c < 4; c++) sacc[r][c] += av[r] * bv[c];
        }

        const int gj0 = kb * 64 + (tc << 2);
#pragma unroll
        for (int r = 0; r < 8; r++) {
            int il = (r < 4) ? ((tr << 2) + r) : (64 + (tr << 2) + r - 4);
            int gi = qb * 128 + il;
            float mrow = -INFINITY;
#pragma unroll
            for (int c = 0; c < 4; c++) {
                float s_ = floorf(sacc[r][c] / SQRT_DM);
                if (gj0 + c > gi) s_ = -INFINITY;
                sacc[r][c] = s_;
                mrow = fmaxf(mrow, s_);
            }
#pragma unroll
            for (int off = 8; off >= 1; off >>= 1)
                mrow = fmaxf(mrow, __shfl_xor_sync(0xffffffffu, mrow, off));

            float mnew = fmaxf(m_[r], mrow);
            float f = __expf(m_[r] - mnew);
            m_[r] = mnew;

            float rs = 0.f;
#pragma unroll
            for (int c = 0; c < 4; c++) {
                float p = __expf(sacc[r][c] - mnew);
                rs += p;
                Ps[((tc << 2) + c) * PS_LD + il] = p;
            }
#pragma unroll
            for (int off = 8; off >= 1; off >>= 1)
                rs += __shfl_xor_sync(0xffffffffu, rs, off);

            l_[r] = l_[r] * f + rs;
#pragma unroll
            for (int c = 0; c < 8; c++) o_[r][c] *= f;
        }
        __syncthreads();

#pragma unroll 2
        for (int j = 0; j < 64; j++) {
            const float* pr = Ps + j * PS_LD + (tr << 2);
            const float* vr = Vs + j * 128 + (tc << 2);
            float av[8] = {pr[0], pr[1], pr[2], pr[3],
                           pr[64], pr[65], pr[66], pr[67]};
            float bv[8] = {vr[0], vr[1], vr[2], vr[3],
                           vr[64], vr[65], vr[66], vr[67]};
#pragma unroll
            for (int r = 0; r < 8; r++)
#pragma unroll
                for (int c = 0; c < 8; c++) o_[r][c] += av[r] * bv[c];
        }
    }

    float* op = g_o + base + (size_t)qb * 128 * DKH;
#pragma unroll
    for (int r = 0; r < 8; r++) {
        int il = (r < 4) ? ((tr << 2) + r) : (64 + (tr << 2) + r - 4);
        float inv = 1.0f / l_[r];
#pragma unroll
        for (int jh = 0; jh < 2; jh++) {
            int col = (jh ? (64 + (tc << 2)) : (tc << 2));
            float4 w;
            w.x = o_[r][jh * 4 + 0] * inv;
            w.y = o_[r][jh * 4 + 1] * inv;
            w.z = o_[r][jh * 4 + 2] * inv;
            w.w = o_[r][jh * 4 + 3] * inv;
            *(float4*)(op + (size_t)il * DKH + col) = w;
        }
    }
}

// ---------------------------------------------------------------------------
extern "C" void kernel_launch(void* const* d_in, const int* in_sizes, int n_in,
                              void* d_out, int out_size)
{
    const float* key   = (const float*)d_in[0];
    const float* query = (const float*)d_in[1];
    const float* value = (const float*)d_in[2];
    const float* Wq = (const float*)d_in[4];
    const float* bq = (const float*)d_in[5];
    const float* Wk = (const float*)d_in[6];
    const float* bk = (const float*)d_in[7];
    const float* Wv = (const float*)d_in[8];
    const float* bv = (const float*)d_in[9];
    const float* Wo = (const float*)d_in[10];
    const float* bo = (const float*)d_in[11];
    float* out = (float*)d_out;

    float *gq, *gk, *gv, *go;
    __nv_bfloat16 *xh, *xl, *wh, *wl;
    cudaGetSymbolAddress((void**)&gq, g_q);
    cudaGetSymbolAddress((void**)&gk, g_k);
    cudaGetSymbolAddress((void**)&gv, g_v);
    cudaGetSymbolAddress((void**)&go, g_o);
    cudaGetSymbolAddress((void**)&xh, g_xh);
    cudaGetSymbolAddress((void**)&xl, g_xl);
    cudaGetSymbolAddress((void**)&wh, g_wh);
    cudaGetSymbolAddress((void**)&wl, g_wl);

    cudaFuncSetAttribute(gemm_bf16x3,
                         cudaFuncAttributeMaxDynamicSharedMemorySize, GEMM_SMEM);
    const int attn_smem = ATTN_SMEM_FLOATS * (int)sizeof(float);
    cudaFuncSetAttribute(attn_kernel,
                         cudaFuncAttributeMaxDynamicSharedMemorySize, attn_smem);

    const int nx4 = MROWS * DMODEL / 4;
    const int nw4 = DMODEL * DMODEL / 4;
    dim3 gfp32(DMODEL / 128, MROWS / 128);       // (16, 32)
    dim3 gmma(DMODEL / GB_BN, MROWS / GB_BM);    // (16, 32)

    // Q/K projections: floor-critical -> fp32 SIMT (R1-identical numerics)
    gemm_nt_bias<<<gfp32, 256>>>(query, Wq, bq, gq);
    gemm_nt_bias<<<gfp32, 256>>>(key,   Wk, bk, gk);

    // V projection: smooth -> bf16x3 mma (direct accumulation)
    split2_bf16<<<nx4 / 256, 256>>>(value, xh, xl, nx4);
    split2_bf16<<<nw4 / 256, 256>>>(Wv, wh, wl, nw4);
    gemm_bf16x3<<<gmma, 256, GEMM_SMEM>>>(xh, xl, wh, wl, bv, gv);

    // Attention (fp32, unchanged)
    attn_kernel<<<dim3(S_LEN / 128, BATCH * NHEADS), 256, attn_smem>>>();

    // Output projection: smooth -> bf16x3 mma (direct accumulation)
    split2_bf16<<<nx4 / 256, 256>>>(go, xh, xl, nx4);
    split2_bf16<<<nw4 / 256, 256>>>(Wo, wh, wl, nw4);
    gemm_bf16x3<<<gmma, 256, GEMM_SMEM>>>(xh, xl, wh, wl, bo, out);
}